// round 1
// baseline (speedup 1.0000x reference)
#include <cuda_runtime.h>
#include <cuda_bf16.h>
#include <math.h>

// ---------------- problem constants ----------------
#define NB 32768            // batch
#define NSF (2*NB)          // sample-frames
#define FEAT_K 592          // 578 padded to 16
#define COMB_K 136          // 132 padded to 8

// ---------------- device scratch (static, no allocs) ----------------
__device__ float g_feats[(size_t)NSF * FEAT_K];   // ~155 MB
__device__ float g_emb[(size_t)NSF * 64];
__device__ int   g_dir[NSF];
__device__ float g_pos[NSF * 2];
__device__ float g_comb[(size_t)NB * COMB_K];
__device__ float g_projwt[FEAT_K * 64];           // [k][e], zero-padded k>=578
__device__ float g_h1wt[COMB_K * 128];            // [k][o], zero-padded k>=132
__device__ float g_h2wt[128 * 128];               // [k][o]

// ---------------- kernel: weight transposes ----------------
__global__ void prep_kernel(const float* __restrict__ projw,
                            const float* __restrict__ h1w,
                            const float* __restrict__ h2w) {
    int i = blockIdx.x * 256 + threadIdx.x;
    const int N1 = FEAT_K * 64;
    const int N2 = COMB_K * 128;
    const int N3 = 128 * 128;
    if (i < N1) {
        int k = i / 64, e = i % 64;
        g_projwt[i] = (k < 578) ? projw[e * 578 + k] : 0.f;
    } else if (i < N1 + N2) {
        int j = i - N1;
        int k = j / 128, o = j % 128;
        g_h1wt[j] = (k < 132) ? h1w[o * 132 + k] : 0.f;
    } else if (i < N1 + N2 + N3) {
        int j = i - N1 - N2;
        int k = j / 128, o = j % 128;
        g_h2wt[j] = h2w[o * 128 + k];
    }
}

// ---------------- kernel: conv encoder (warp per sample-frame) ----------------
// dynamic smem layout (floats):
//  sw1[192] sb1[16] sw2t[2048] sb2[32] sw3t[8192] sb3[64]  (10544)
//  per warp (8): xin[243] p1[576] p2[512]  = 1331 each
#define ENC_WARPS 8
#define ENC_SMEM_FLOATS (10544 + ENC_WARPS * 1331)

__global__ void __launch_bounds__(256) encode_kernel(
    const int* __restrict__ frame, const int* __restrict__ ccol, const int* __restrict__ cobj,
    const float* __restrict__ w1g, const float* __restrict__ b1g,
    const float* __restrict__ w2g, const float* __restrict__ b2g,
    const float* __restrict__ w3g, const float* __restrict__ b3g)
{
    extern __shared__ float smem[];
    float* sw1  = smem;
    float* sb1  = sw1 + 192;
    float* sw2t = sb1 + 16;
    float* sb2  = sw2t + 2048;
    float* sw3t = sb2 + 32;
    float* sb3  = sw3t + 8192;
    float* swarp = sb3 + 64;

    int tid = threadIdx.x;
    for (int i = tid; i < 192; i += 256) sw1[i] = w1g[i];
    if (tid < 16) sb1[tid] = b1g[tid];
    for (int i = tid; i < 2048; i += 256) sw2t[(i & 63) * 32 + (i >> 6)] = w2g[i];
    if (tid < 32) sb2[tid] = b2g[tid];
    for (int i = tid; i < 8192; i += 256) sw3t[(i & 127) * 64 + (i >> 7)] = w3g[i];
    if (tid < 64) sb3[tid] = b3g[tid];
    __syncthreads();

    int warp = tid >> 5, lane = tid & 31;
    int sf = blockIdx.x * ENC_WARPS + warp;   // grid sized exactly

    float* xin = swarp + warp * 1331;   // [3][9][9] padded
    float* p1  = xin + 243;             // [16][6][6] padded
    float* p2  = p1 + 576;              // [32][4][4] padded

    const int* fb = frame + (size_t)sf * 147;

    // zero padded input, then fill interior (HWC -> CHW)
    for (int i = lane; i < 243; i += 32) xin[i] = 0.f;
    __syncwarp();
    for (int i = lane; i < 147; i += 32) {
        int y = i / 21, r = i % 21, x = r / 3, c = r % 3;
        xin[c * 81 + (y + 1) * 9 + (x + 1)] = (float)fb[i];
    }
    // dir/pos via ballot (first row-major position where ch0 == 10)
    {
        int v0 = fb[lane * 3];
        unsigned m0 = __ballot_sync(0xffffffffu, v0 == 10);
        int p2i = 32 + lane;
        int v1 = (p2i < 49) ? fb[p2i * 3] : 0;
        unsigned m1 = __ballot_sync(0xffffffffu, (p2i < 49) && (v1 == 10));
        if (lane == 0) {
            int idx = m0 ? (__ffs(m0) - 1) : (m1 ? (31 + __ffs(m1)) : -1);
            int d = 0; float py = 0.5f, px = 0.5f;
            if (idx >= 0) {
                d = fb[idx * 3 + 2] & 3;
                py = (float)(idx / 7) * (1.f / 6.f);
                px = (float)(idx % 7) * (1.f / 6.f);
            }
            g_dir[sf] = d;
            g_pos[sf * 2 + 0] = py;
            g_pos[sf * 2 + 1] = px;
        }
    }
    __syncwarp();

    // -------- conv1 (3->16, k2 pad1, out 8x8) + relu + pool2 -> p1 interior [16][4][4]
    for (int i = lane; i < 576; i += 32) p1[i] = 0.f;
    __syncwarp();
    {
        int c = lane & 15, half = lane >> 4;
        float w[12];
        #pragma unroll
        for (int j = 0; j < 12; j++) w[j] = sw1[c * 12 + j];
        float bias = sb1[c];
        #pragma unroll
        for (int t8 = 0; t8 < 8; t8++) {
            int pos = half * 8 + t8;
            int py = pos >> 2, px = pos & 3;
            float m = 0.f;
            #pragma unroll
            for (int dy = 0; dy < 2; dy++)
            #pragma unroll
            for (int dx = 0; dx < 2; dx++) {
                int oy = 2 * py + dy, ox = 2 * px + dx;
                float s = bias;
                #pragma unroll
                for (int ic = 0; ic < 3; ic++) {
                    const float* xp = xin + ic * 81 + oy * 9 + ox;
                    s += w[ic * 4 + 0] * xp[0] + w[ic * 4 + 1] * xp[1]
                       + w[ic * 4 + 2] * xp[9] + w[ic * 4 + 3] * xp[10];
                }
                m = fmaxf(m, s);
            }
            p1[c * 36 + (py + 1) * 6 + (px + 1)] = m;
        }
    }
    __syncwarp();

    // -------- conv2 (16->32) + relu + pool -> p2 interior [32][2][2]; lane = channel
    for (int i = lane; i < 512; i += 32) p2[i] = 0.f;
    {
        float acc[16];
        #pragma unroll
        for (int i = 0; i < 16; i++) acc[i] = 0.f;
        #pragma unroll 4
        for (int ic = 0; ic < 16; ic++) {
            float in[25];
            const float* pp = p1 + ic * 36;
            #pragma unroll
            for (int yy = 0; yy < 5; yy++)
                #pragma unroll
                for (int xx = 0; xx < 5; xx++) in[yy * 5 + xx] = pp[yy * 6 + xx];
            float wa = sw2t[(ic * 4 + 0) * 32 + lane];
            float wb = sw2t[(ic * 4 + 1) * 32 + lane];
            float wc = sw2t[(ic * 4 + 2) * 32 + lane];
            float wd = sw2t[(ic * 4 + 3) * 32 + lane];
            #pragma unroll
            for (int oy = 0; oy < 4; oy++)
                #pragma unroll
                for (int ox = 0; ox < 4; ox++) {
                    acc[oy * 4 + ox] += wa * in[oy * 5 + ox] + wb * in[oy * 5 + ox + 1]
                                      + wc * in[(oy + 1) * 5 + ox] + wd * in[(oy + 1) * 5 + ox + 1];
                }
        }
        float bias = sb2[lane];
        __syncwarp();   // zeroing of p2 complete before interior writes
        #pragma unroll
        for (int py = 0; py < 2; py++)
            #pragma unroll
            for (int px = 0; px < 2; px++) {
                float m = fmaxf(fmaxf(acc[(2 * py) * 4 + 2 * px],     acc[(2 * py) * 4 + 2 * px + 1]),
                                fmaxf(acc[(2 * py + 1) * 4 + 2 * px], acc[(2 * py + 1) * 4 + 2 * px + 1]));
                p2[lane * 16 + (py + 1) * 4 + (px + 1)] = fmaxf(m + bias, 0.f);
            }
    }
    __syncwarp();

    // -------- conv3 (32->64, out 3x3) + relu -> feats global; lane owns channels lane, lane+32
    {
        float a0[9], a1[9];
        #pragma unroll
        for (int i = 0; i < 9; i++) { a0[i] = 0.f; a1[i] = 0.f; }
        #pragma unroll 4
        for (int ic = 0; ic < 32; ic++) {
            float in[16];
            const float* pp = p2 + ic * 16;
            #pragma unroll
            for (int i = 0; i < 16; i++) in[i] = pp[i];
            float wA0 = sw3t[(ic * 4 + 0) * 64 + lane];
            float wA1 = sw3t[(ic * 4 + 1) * 64 + lane];
            float wA2 = sw3t[(ic * 4 + 2) * 64 + lane];
            float wA3 = sw3t[(ic * 4 + 3) * 64 + lane];
            float wB0 = sw3t[(ic * 4 + 0) * 64 + lane + 32];
            float wB1 = sw3t[(ic * 4 + 1) * 64 + lane + 32];
            float wB2 = sw3t[(ic * 4 + 2) * 64 + lane + 32];
            float wB3 = sw3t[(ic * 4 + 3) * 64 + lane + 32];
            #pragma unroll
            for (int oy = 0; oy < 3; oy++)
                #pragma unroll
                for (int ox = 0; ox < 3; ox++) {
                    float i00 = in[oy * 4 + ox],       i01 = in[oy * 4 + ox + 1];
                    float i10 = in[(oy + 1) * 4 + ox], i11 = in[(oy + 1) * 4 + ox + 1];
                    a0[oy * 3 + ox] += wA0 * i00 + wA1 * i01 + wA2 * i10 + wA3 * i11;
                    a1[oy * 3 + ox] += wB0 * i00 + wB1 * i01 + wB2 * i10 + wB3 * i11;
                }
        }
        float* fbase = g_feats + (size_t)sf * FEAT_K;
        float b0 = sb3[lane], b1v = sb3[lane + 32];
        #pragma unroll
        for (int p = 0; p < 9; p++) {
            fbase[lane * 9 + p]        = fmaxf(a0[p] + b0, 0.f);
            fbase[(lane + 32) * 9 + p] = fmaxf(a1[p] + b1v, 0.f);
        }
        if (lane == 0) {
            fbase[576] = (float)ccol[sf];
            fbase[577] = (float)cobj[sf];
        }
        if (lane < 14) fbase[578 + lane] = 0.f;
    }
}

// ---------------- kernel: proj GEMM  emb[2B,64] = relu(feats * Wt + b) ----------------
__global__ void __launch_bounds__(256) proj_kernel(const float* __restrict__ projb)
{
    __shared__ float As[16][68];   // [k][m]
    __shared__ float Bs[16][64];   // [k][n]
    int tid = threadIdx.x;
    int m0 = blockIdx.x * 64;
    int tx = tid & 15, ty = tid >> 4;
    float acc[4][4];
    #pragma unroll
    for (int i = 0; i < 4; i++)
        #pragma unroll
        for (int j = 0; j < 4; j++) acc[i][j] = 0.f;

    for (int k0 = 0; k0 < FEAT_K; k0 += 16) {
        {
            int m = tid >> 2, kq = (tid & 3) * 4;
            float4 av = *reinterpret_cast<const float4*>(g_feats + (size_t)(m0 + m) * FEAT_K + k0 + kq);
            As[kq + 0][m] = av.x; As[kq + 1][m] = av.y; As[kq + 2][m] = av.z; As[kq + 3][m] = av.w;
        }
        {
            int k = tid >> 4, nq = (tid & 15) * 4;
            *reinterpret_cast<float4*>(&Bs[k][nq]) =
                *reinterpret_cast<const float4*>(g_projwt + (k0 + k) * 64 + nq);
        }
        __syncthreads();
        #pragma unroll
        for (int k = 0; k < 16; k++) {
            float a[4], b[4];
            #pragma unroll
            for (int i = 0; i < 4; i++) a[i] = As[k][ty * 4 + i];
            #pragma unroll
            for (int j = 0; j < 4; j++) b[j] = Bs[k][tx * 4 + j];
            #pragma unroll
            for (int i = 0; i < 4; i++)
                #pragma unroll
                for (int j = 0; j < 4; j++) acc[i][j] += a[i] * b[j];
        }
        __syncthreads();
    }
    #pragma unroll
    for (int i = 0; i < 4; i++) {
        int m = m0 + ty * 4 + i;
        #pragma unroll
        for (int j = 0; j < 4; j++) {
            int n = tx * 4 + j;
            g_emb[(size_t)m * 64 + n] = fmaxf(acc[i][j] + projb[n], 0.f);
        }
    }
}

// ---------------- kernel: build comb[B,136] ----------------
__global__ void comb_kernel()
{
    int i = blockIdx.x * 256 + threadIdx.x;
    if (i >= NB * COMB_K) return;
    int b = i / COMB_K, k = i % COMB_K;
    float v;
    if (k < 64)       v = g_emb[(size_t)b * 64 + k];
    else if (k < 128) v = g_emb[(size_t)(NB + b) * 64 + (k - 64)];
    else if (k < 130) {
        int delta = ((g_dir[NB + b] - g_dir[b]) + 4) & 3;
        float ang = (float)delta * (2.0f * 3.14159f / 4.0f);
        v = (k == 128) ? sinf(ang) : cosf(ang);
    }
    else if (k == 130) v = g_pos[(NB + b) * 2 + 0] - g_pos[b * 2 + 0];
    else if (k == 131) v = g_pos[(NB + b) * 2 + 1] - g_pos[b * 2 + 1];
    else v = 0.f;
    g_comb[i] = v;
}

// ---------------- kernel: fused MLP h1 -> LN -> relu -> h2 -> relu -> h3 ----------------
// dynamic smem floats: As[136*129] + Bs[136*128] + Hs[128*129] + sh3[896]
#define MLP_AS (136 * 129)
#define MLP_BS (136 * 128)
#define MLP_HS (128 * 129)
#define MLP_SMEM_FLOATS (MLP_AS + MLP_BS + MLP_HS + 896)

__global__ void __launch_bounds__(256) mlp_kernel(
    const float* __restrict__ h1b, const float* __restrict__ lng, const float* __restrict__ lnb,
    const float* __restrict__ h2b, const float* __restrict__ h3w, const float* __restrict__ h3b,
    float* __restrict__ out)
{
    extern __shared__ float smem[];
    float* As  = smem;                 // comb^T [k][m] stride 129; later h2^T
    float* Bs  = As + MLP_AS;          // weights [k][n] stride 128
    float* Hs  = Bs + MLP_BS;          // h^T [feature][m] stride 129
    float* sh3 = Hs + MLP_HS;          // h3_w [7][128]

    int tid = threadIdx.x;
    int m0 = blockIdx.x * 128;

    for (int i = tid; i < 128 * COMB_K; i += 256) {
        int m = i / COMB_K, k = i % COMB_K;
        As[k * 129 + m] = g_comb[(size_t)(m0 + m) * COMB_K + k];
    }
    for (int i = tid; i < COMB_K * 128; i += 256) Bs[i] = g_h1wt[i];
    for (int i = tid; i < 896; i += 256) sh3[i] = h3w[i];
    __syncthreads();

    int tx = tid & 15, ty = tid >> 4;

    // ---- GEMM1: h[128m][128n] = comb * h1wt
    float acc[8][8];
    #pragma unroll
    for (int i = 0; i < 8; i++)
        #pragma unroll
        for (int j = 0; j < 8; j++) acc[i][j] = 0.f;
    for (int k = 0; k < COMB_K; k++) {
        float a[8], b[8];
        #pragma unroll
        for (int i = 0; i < 8; i++) a[i] = As[k * 129 + ty * 8 + i];
        #pragma unroll
        for (int j = 0; j < 8; j++) b[j] = Bs[k * 128 + tx * 8 + j];
        #pragma unroll
        for (int i = 0; i < 8; i++)
            #pragma unroll
            for (int j = 0; j < 8; j++) acc[i][j] += a[i] * b[j];
    }
    // write pre-LN h (+bias) transposed into Hs[feature][m]
    #pragma unroll
    for (int j = 0; j < 8; j++) {
        int n = tx * 8 + j;
        float bn = h1b[n];
        #pragma unroll
        for (int i = 0; i < 8; i++) {
            int m = ty * 8 + i;
            Hs[n * 129 + m] = acc[i][j] + bn;
        }
    }
    __syncthreads();

    // load h2 weights (Bs free now)
    for (int i = tid; i < 128 * 128; i += 256) Bs[i] = g_h2wt[i];
    // LayerNorm + relu, one thread per sample row
    if (tid < 128) {
        int m = tid;
        float s = 0.f, s2 = 0.f;
        for (int k = 0; k < 128; k++) {
            float v = Hs[k * 129 + m];
            s += v; s2 += v * v;
        }
        float mu = s * (1.f / 128.f);
        float var = s2 * (1.f / 128.f) - mu * mu;
        float rs = rsqrtf(var + 1e-5f);
        for (int k = 0; k < 128; k++) {
            float v = Hs[k * 129 + m];
            Hs[k * 129 + m] = fmaxf((v - mu) * rs * lng[k] + lnb[k], 0.f);
        }
    }
    __syncthreads();

    // ---- GEMM2: h2 = relu(h * h2wt + b)
    float acc2[8][8];
    #pragma unroll
    for (int i = 0; i < 8; i++)
        #pragma unroll
        for (int j = 0; j < 8; j++) acc2[i][j] = 0.f;
    for (int k = 0; k < 128; k++) {
        float a[8], b[8];
        #pragma unroll
        for (int i = 0; i < 8; i++) a[i] = Hs[k * 129 + ty * 8 + i];
        #pragma unroll
        for (int j = 0; j < 8; j++) b[j] = Bs[k * 128 + tx * 8 + j];
        #pragma unroll
        for (int i = 0; i < 8; i++)
            #pragma unroll
            for (int j = 0; j < 8; j++) acc2[i][j] += a[i] * b[j];
    }
    __syncthreads();   // everyone done reading As (long since) — reuse as h2^T
    #pragma unroll
    for (int j = 0; j < 8; j++) {
        int n = tx * 8 + j;
        float bn = h2b[n];
        #pragma unroll
        for (int i = 0; i < 8; i++) {
            int m = ty * 8 + i;
            As[n * 129 + m] = fmaxf(acc2[i][j] + bn, 0.f);
        }
    }
    __syncthreads();

    // ---- h3: out[m][7]
    if (tid < 128) {
        int m = tid;
        #pragma unroll
        for (int j = 0; j < 7; j++) {
            float s = h3b[j];
            for (int k = 0; k < 128; k++) s += As[k * 129 + m] * sh3[j * 128 + k];
            out[(size_t)(m0 + m) * 7 + j] = s;
        }
    }
}

// ---------------- launch ----------------
extern "C" void kernel_launch(void* const* d_in, const int* in_sizes, int n_in,
                              void* d_out, int out_size)
{
    const int*   frame = (const int*)d_in[0];
    const int*   ccol  = (const int*)d_in[1];
    const int*   cobj  = (const int*)d_in[2];
    const float* c1w = (const float*)d_in[3];
    const float* c1b = (const float*)d_in[4];
    const float* c2w = (const float*)d_in[5];
    const float* c2b = (const float*)d_in[6];
    const float* c3w = (const float*)d_in[7];
    const float* c3b = (const float*)d_in[8];
    const float* pw  = (const float*)d_in[9];
    const float* pb  = (const float*)d_in[10];
    const float* h1w = (const float*)d_in[11];
    const float* h1b = (const float*)d_in[12];
    const float* lng = (const float*)d_in[13];
    const float* lnb = (const float*)d_in[14];
    const float* h2w = (const float*)d_in[15];
    const float* h2b = (const float*)d_in[16];
    const float* h3w = (const float*)d_in[17];
    const float* h3b = (const float*)d_in[18];
    float* out = (float*)d_out;

    cudaFuncSetAttribute(encode_kernel, cudaFuncAttributeMaxDynamicSharedMemorySize,
                         ENC_SMEM_FLOATS * (int)sizeof(float));
    cudaFuncSetAttribute(mlp_kernel, cudaFuncAttributeMaxDynamicSharedMemorySize,
                         MLP_SMEM_FLOATS * (int)sizeof(float));

    {
        int total = FEAT_K * 64 + COMB_K * 128 + 128 * 128;
        prep_kernel<<<(total + 255) / 256, 256>>>(pw, h1w, h2w);
    }
    encode_kernel<<<NSF / ENC_WARPS, 256, ENC_SMEM_FLOATS * sizeof(float)>>>(
        frame, ccol, cobj, c1w, c1b, c2w, c2b, c3w, c3b);
    proj_kernel<<<NSF / 64, 256>>>(pb);
    {
        int total = NB * COMB_K;
        comb_kernel<<<(total + 255) / 256, 256>>>();
    }
    mlp_kernel<<<NB / 128, 256, MLP_SMEM_FLOATS * sizeof(float)>>>(
        h1b, lng, lnb, h2b, h3w, h3b, out);
}